// round 13
// baseline (speedup 1.0000x reference)
#include <cuda_runtime.h>

#define S      1024
#define BATCH  4096
#define HID    4
#define OBSR   8
#define OUTD   8

// Scratch: u = relu(BN1(...)) [S,B,4] and h_t [S,B,4] (AoS float4 per element).
__device__ float4 g_U[S * BATCH];   // 64 MB
__device__ float4 g_H[S * BATCH];   // 64 MB

// Fast activations for the recurrence: single-MUFU tanh.
__device__ __forceinline__ float tanh_a(float x) {
    float y; asm("tanh.approx.f32 %0, %1;" : "=f"(y) : "f"(x)); return y;
}
__device__ __forceinline__ float sig_a(float x) {
    return fmaf(tanh_a(0.5f * x), 0.5f, 0.5f);   // sig(x) = 0.5*tanh(x/2)+0.5
}

// ---------------------------------------------------------------------------
// Pass 1 (measured-best layout, 68us): one CTA (512 thr) per timestep,
// 8 elements/thread cached in regs. z = obs@W_eff + ts@W_ts + b_eff; BN1; relu.
// ---------------------------------------------------------------------------
__global__ void __launch_bounds__(512)
pass1_kernel(const float* __restrict__ obs, const float* __restrict__ ts,
             const float* __restrict__ Wobs, const float* __restrict__ bobs,
             const float* __restrict__ Win,  const float* __restrict__ bin,
             const float* __restrict__ g1,   const float* __restrict__ b1)
{
    __shared__ float sWe[8][4];
    __shared__ float sWt[4][4];
    __shared__ float sbe[4];
    __shared__ float sred[16 * 8];
    __shared__ float sscale[4], sshift[4];

    const int t   = blockIdx.x;
    const int tid = threadIdx.x;   // 512

    if (tid < 32) {
        int k = tid >> 2, j = tid & 3;
        float acc = 0.f;
        #pragma unroll
        for (int m = 0; m < 8; m++) acc += Wobs[k * 8 + m] * Win[m * 4 + j];
        sWe[k][j] = acc;
    } else if (tid < 48) {
        int k = (tid - 32) >> 2, j = tid & 3;
        sWt[k][j] = Win[(8 + k) * 4 + j];
    } else if (tid < 52) {
        int j = tid - 48;
        float acc = bin[j];
        #pragma unroll
        for (int m = 0; m < 8; m++) acc += bobs[m] * Win[m * 4 + j];
        sbe[j] = acc;
    }
    __syncthreads();

    float z[8][4];
    float ps[4] = {0.f, 0.f, 0.f, 0.f};
    float pq[4] = {0.f, 0.f, 0.f, 0.f};

    const float4* obs4 = ((const float4*)obs) + (size_t)t * BATCH * 2;
    const float4* ts4  = ((const float4*)ts)  + (size_t)t * BATCH;

    #pragma unroll
    for (int s = 0; s < 8; s++) {
        int b = tid + s * 512;
        float4 o0 = obs4[b * 2 + 0];
        float4 o1 = obs4[b * 2 + 1];
        float4 tv = ts4[b];
        #pragma unroll
        for (int j = 0; j < 4; j++) {
            float a = sbe[j];
            a += o0.x * sWe[0][j] + o0.y * sWe[1][j] + o0.z * sWe[2][j] + o0.w * sWe[3][j];
            a += o1.x * sWe[4][j] + o1.y * sWe[5][j] + o1.z * sWe[6][j] + o1.w * sWe[7][j];
            a += tv.x * sWt[0][j] + tv.y * sWt[1][j] + tv.z * sWt[2][j] + tv.w * sWt[3][j];
            z[s][j] = a;
            ps[j] += a;
            pq[j] += a * a;
        }
    }

    const int lane = tid & 31, wrp = tid >> 5;
    #pragma unroll
    for (int j = 0; j < 4; j++) {
        #pragma unroll
        for (int off = 16; off; off >>= 1) {
            ps[j] += __shfl_xor_sync(0xffffffffu, ps[j], off);
            pq[j] += __shfl_xor_sync(0xffffffffu, pq[j], off);
        }
    }
    if (lane == 0) {
        #pragma unroll
        for (int j = 0; j < 4; j++) { sred[wrp * 8 + j] = ps[j]; sred[wrp * 8 + 4 + j] = pq[j]; }
    }
    __syncthreads();
    if (tid < 4) {
        float s0 = 0.f, q0 = 0.f;
        #pragma unroll
        for (int w = 0; w < 16; w++) { s0 += sred[w * 8 + tid]; q0 += sred[w * 8 + 4 + tid]; }
        float m  = s0 * (1.0f / BATCH);
        float v  = q0 * (1.0f / BATCH) - m * m;
        float sc = g1[tid] * rsqrtf(v + 1e-5f);
        sscale[tid] = sc;
        sshift[tid] = b1[tid] - m * sc;
    }
    __syncthreads();

    float4* Up = g_U + (size_t)t * BATCH;
    #pragma unroll
    for (int s = 0; s < 8; s++) {
        int b = tid + s * 512;
        float4 u;
        u.x = fmaxf(z[s][0] * sscale[0] + sshift[0], 0.f);
        u.y = fmaxf(z[s][1] * sscale[1] + sshift[1], 0.f);
        u.z = fmaxf(z[s][2] * sscale[2] + sshift[2], 0.f);
        u.w = fmaxf(z[s][3] * sscale[3] + sshift[3], 0.f);
        Up[b] = u;
    }
}

// ---------------------------------------------------------------------------
// Pass 2: sequential LSTM recurrence, TWO independent chains per thread.
// The single-chain version runs ~260 cyc/step against a ~90-cyc dependency
// chain and ~96-cyc issue floor — exposed bubbles. Chain B's independent
// issue fills chain A's stalls.
// 64 blocks x 128 threads (4 warps/block -> one warp per SMSP — the correct
// mapping R6 got wrong). lane = e*4 + k; warp covers 16 elements
// (chain0 = base+e, chain1 = base+8+e).
// ---------------------------------------------------------------------------
__global__ void __launch_bounds__(128, 1)
pass2_kernel(const float* __restrict__ Wih, const float* __restrict__ Whh,
             const float* __restrict__ bih, const float* __restrict__ bhh)
{
    const int lane = threadIdx.x & 31;
    const int wid  = threadIdx.x >> 5;     // 0..3 -> SMSP
    const int e    = lane >> 2;            // 0..7
    const int k    = lane & 3;             // gate-row slice
    const int b0   = blockIdx.x * 64 + wid * 16 + e;
    const int b1   = b0 + 8;

    // Gate rows for this lane: i=k, f=4+k, g=8+k, o=12+k.
    float wiI[4], wiF[4], wiG[4], wiO[4];       // u-weights (natural order)
    float whI[4], whF[4], whG[4], whO[4];       // h-weights permuted: [d] = row[k^d]
    #pragma unroll
    for (int m = 0; m < 4; m++) {
        wiI[m] = Wih[(k     ) * 4 + m];
        wiF[m] = Wih[(4 + k ) * 4 + m];
        wiG[m] = Wih[(8 + k ) * 4 + m];
        wiO[m] = Wih[(12 + k) * 4 + m];
        int km = k ^ m;
        whI[m] = Whh[(k     ) * 4 + km];
        whF[m] = Whh[(4 + k ) * 4 + km];
        whG[m] = Whh[(8 + k ) * 4 + km];
        whO[m] = Whh[(12 + k) * 4 + km];
    }
    const float bI = bih[k]      + bhh[k];
    const float bF = bih[4 + k]  + bhh[4 + k];
    const float bG = bih[8 + k]  + bhh[8 + k];
    const float bO = bih[12 + k] + bhh[12 + k];

    float h0 = 0.f, c0 = 0.f;
    float h1 = 0.f, c1 = 0.f;

    const float4* __restrict__ up0 = g_U + b0;
    const float4* __restrict__ up1 = g_U + b1;
    float* __restrict__ hp0 = ((float*)g_H) + (size_t)b0 * 4 + k;
    float* __restrict__ hp1 = ((float*)g_H) + (size_t)b1 * 4 + k;

    float4 ra[8], rb[8];
    #pragma unroll
    for (int i = 0; i < 8; i++) { ra[i] = up0[(size_t)i * BATCH]; rb[i] = up1[(size_t)i * BATCH]; }
    up0 += (size_t)8 * BATCH;
    up1 += (size_t)8 * BATCH;

#define P2_STEP(i, PF)                                                         \
    {                                                                          \
        float4 uA = ra[i], uB = rb[i];                                         \
        if (PF) { ra[i] = up0[(size_t)(i) * BATCH];                            \
                  rb[i] = up1[(size_t)(i) * BATCH]; }                          \
        /* u-parts, both chains (independent filler work) */                   \
        float aI0 = bI + uA.x * wiI[0] + uA.y * wiI[1] + uA.z * wiI[2] + uA.w * wiI[3]; \
        float aI1 = bI + uB.x * wiI[0] + uB.y * wiI[1] + uB.z * wiI[2] + uB.w * wiI[3]; \
        float aF0 = bF + uA.x * wiF[0] + uA.y * wiF[1] + uA.z * wiF[2] + uA.w * wiF[3]; \
        float aF1 = bF + uB.x * wiF[0] + uB.y * wiF[1] + uB.z * wiF[2] + uB.w * wiF[3]; \
        float aG0 = bG + uA.x * wiG[0] + uA.y * wiG[1] + uA.z * wiG[2] + uA.w * wiG[3]; \
        float aG1 = bG + uB.x * wiG[0] + uB.y * wiG[1] + uB.z * wiG[2] + uB.w * wiG[3]; \
        float aO0 = bO + uA.x * wiO[0] + uA.y * wiO[1] + uA.z * wiO[2] + uA.w * wiO[3]; \
        float aO1 = bO + uB.x * wiO[0] + uB.y * wiO[1] + uB.z * wiO[2] + uB.w * wiO[3]; \
        /* depth-1 gathers of peer h, both chains */                           \
        float ha0 = __shfl_xor_sync(0xffffffffu, h0, 1);                       \
        float ha1 = __shfl_xor_sync(0xffffffffu, h1, 1);                       \
        float hb0 = __shfl_xor_sync(0xffffffffu, h0, 2);                       \
        float hb1 = __shfl_xor_sync(0xffffffffu, h1, 2);                       \
        float hc0 = __shfl_xor_sync(0xffffffffu, h0, 3);                       \
        float hc1 = __shfl_xor_sync(0xffffffffu, h1, 3);                       \
        /* tree-structured hh parts */                                         \
        float gI0 = aI0 + ((h0 * whI[0] + ha0 * whI[1]) + (hb0 * whI[2] + hc0 * whI[3])); \
        float gI1 = aI1 + ((h1 * whI[0] + ha1 * whI[1]) + (hb1 * whI[2] + hc1 * whI[3])); \
        float gF0 = aF0 + ((h0 * whF[0] + ha0 * whF[1]) + (hb0 * whF[2] + hc0 * whF[3])); \
        float gF1 = aF1 + ((h1 * whF[0] + ha1 * whF[1]) + (hb1 * whF[2] + hc1 * whF[3])); \
        float gG0 = aG0 + ((h0 * whG[0] + ha0 * whG[1]) + (hb0 * whG[2] + hc0 * whG[3])); \
        float gG1 = aG1 + ((h1 * whG[0] + ha1 * whG[1]) + (hb1 * whG[2] + hc1 * whG[3])); \
        float gO0 = aO0 + ((h0 * whO[0] + ha0 * whO[1]) + (hb0 * whO[2] + hc0 * whO[3])); \
        float gO1 = aO1 + ((h1 * whO[0] + ha1 * whO[1]) + (hb1 * whO[2] + hc1 * whO[3])); \
        c0 = sig_a(gF0) * c0 + sig_a(gI0) * tanh_a(gG0);                       \
        c1 = sig_a(gF1) * c1 + sig_a(gI1) * tanh_a(gG1);                       \
        h0 = sig_a(gO0) * tanh_a(c0);                                          \
        h1 = sig_a(gO1) * tanh_a(c1);                                          \
        hp0[0] = h0;  hp0 += (size_t)BATCH * 4;                                \
        hp1[0] = h1;  hp1 += (size_t)BATCH * 4;                                \
    }

    for (int t = 0; t < S - 8; t += 8) {
        #pragma unroll
        for (int i = 0; i < 8; i++) P2_STEP(i, true)
        up0 += (size_t)8 * BATCH;
        up1 += (size_t)8 * BATCH;
    }
    #pragma unroll
    for (int i = 0; i < 8; i++) P2_STEP(i, false)
#undef P2_STEP
}

// ---------------------------------------------------------------------------
// Pass 3: one CTA (1024 thr) per timestep; 4 elements/thread cached in regs.
// BN2 stats over batch, y = BN2(h)@W_out + b_out, stats folded into [4x8]+[8].
// ---------------------------------------------------------------------------
__global__ void __launch_bounds__(1024, 1)
pass3_kernel(float* __restrict__ out,
             const float* __restrict__ g2,   const float* __restrict__ b2,
             const float* __restrict__ Wout, const float* __restrict__ bout)
{
    __shared__ float sred[32 * 8];
    __shared__ float sscale[4], sshift[4];
    __shared__ float sW[4][8];
    __shared__ float sB[8];

    const int t   = blockIdx.x;
    const int tid = threadIdx.x;   // 1024

    const float4* Hp = g_H + (size_t)t * BATCH;

    float4 hv[4];
    float ps[4] = {0.f, 0.f, 0.f, 0.f};
    float pq[4] = {0.f, 0.f, 0.f, 0.f};
    #pragma unroll
    for (int s = 0; s < 4; s++) {
        int b = tid + s * 1024;
        float4 v = Hp[b];
        hv[s] = v;
        ps[0] += v.x; pq[0] += v.x * v.x;
        ps[1] += v.y; pq[1] += v.y * v.y;
        ps[2] += v.z; pq[2] += v.z * v.z;
        ps[3] += v.w; pq[3] += v.w * v.w;
    }

    const int lane = tid & 31, wrp = tid >> 5;
    #pragma unroll
    for (int j = 0; j < 4; j++) {
        #pragma unroll
        for (int off = 16; off; off >>= 1) {
            ps[j] += __shfl_xor_sync(0xffffffffu, ps[j], off);
            pq[j] += __shfl_xor_sync(0xffffffffu, pq[j], off);
        }
    }
    if (lane == 0) {
        #pragma unroll
        for (int j = 0; j < 4; j++) { sred[wrp * 8 + j] = ps[j]; sred[wrp * 8 + 4 + j] = pq[j]; }
    }
    __syncthreads();
    if (tid < 4) {
        float s0 = 0.f, q0 = 0.f;
        #pragma unroll
        for (int w = 0; w < 32; w++) { s0 += sred[w * 8 + tid]; q0 += sred[w * 8 + 4 + tid]; }
        float m  = s0 * (1.0f / BATCH);
        float v  = q0 * (1.0f / BATCH) - m * m;
        float sc = g2[tid] * rsqrtf(v + 1e-5f);
        sscale[tid] = sc;
        sshift[tid] = b2[tid] - m * sc;
    }
    __syncthreads();
    if (tid < 32) {
        int kk = tid >> 3, j = tid & 7;
        sW[kk][j] = sscale[kk] * Wout[kk * 8 + j];
    } else if (tid < 40) {
        int j = tid - 32;
        float acc = bout[j];
        #pragma unroll
        for (int kk = 0; kk < 4; kk++) acc += sshift[kk] * Wout[kk * 8 + j];
        sB[j] = acc;
    }
    __syncthreads();

    float4* out4 = ((float4*)out) + (size_t)t * BATCH * 2;
    #pragma unroll
    for (int s = 0; s < 4; s++) {
        int b = tid + s * 1024;
        float4 v = hv[s];
        float y[8];
        #pragma unroll
        for (int j = 0; j < 8; j++) {
            y[j] = sB[j] + v.x * sW[0][j] + v.y * sW[1][j] + v.z * sW[2][j] + v.w * sW[3][j];
        }
        out4[b * 2 + 0] = make_float4(y[0], y[1], y[2], y[3]);
        out4[b * 2 + 1] = make_float4(y[4], y[5], y[6], y[7]);
    }
}

// ---------------------------------------------------------------------------
extern "C" void kernel_launch(void* const* d_in, const int* in_sizes, int n_in,
                              void* d_out, int out_size)
{
    const float* obs  = (const float*)d_in[0];
    const float* ts   = (const float*)d_in[1];
    const float* Wobs = (const float*)d_in[2];
    const float* bobs = (const float*)d_in[3];
    const float* Win  = (const float*)d_in[4];
    const float* bin  = (const float*)d_in[5];
    const float* g1   = (const float*)d_in[6];
    const float* b1   = (const float*)d_in[7];
    const float* Wih  = (const float*)d_in[8];
    const float* Whh  = (const float*)d_in[9];
    const float* bih  = (const float*)d_in[10];
    const float* bhh  = (const float*)d_in[11];
    const float* g2   = (const float*)d_in[12];
    const float* b2   = (const float*)d_in[13];
    const float* Wout = (const float*)d_in[14];
    const float* bout = (const float*)d_in[15];

    pass1_kernel<<<S, 512>>>(obs, ts, Wobs, bobs, Win, bin, g1, b1);
    pass2_kernel<<<BATCH / 64, 128>>>(Wih, Whh, bih, bhh);
    pass3_kernel<<<S, 1024>>>((float*)d_out, g2, b2, Wout, bout);
}

// round 14
// speedup vs baseline: 1.2343x; 1.2343x over previous
#include <cuda_runtime.h>

#define S      1024
#define BATCH  4096
#define HID    4
#define OBSR   8
#define OUTD   8

// Scratch: u = relu(BN1(...)) [S,B,4] and h_t [S,B,4] (AoS float4 per element).
__device__ float4 g_U[S * BATCH];   // 64 MB
__device__ float4 g_H[S * BATCH];   // 64 MB

// Fast activations for the recurrence: single-MUFU tanh.
__device__ __forceinline__ float tanh_a(float x) {
    float y; asm("tanh.approx.f32 %0, %1;" : "=f"(y) : "f"(x)); return y;
}
__device__ __forceinline__ float sig_a(float x) {
    return fmaf(tanh_a(0.5f * x), 0.5f, 0.5f);   // sig(x) = 0.5*tanh(x/2)+0.5
}

// ---------------------------------------------------------------------------
// Pass 1 (measured-best layout, 68us): one CTA (512 thr) per timestep,
// 8 elements/thread cached in regs. z = obs@W_eff + ts@W_ts + b_eff; BN1; relu.
// ---------------------------------------------------------------------------
__global__ void __launch_bounds__(512)
pass1_kernel(const float* __restrict__ obs, const float* __restrict__ ts,
             const float* __restrict__ Wobs, const float* __restrict__ bobs,
             const float* __restrict__ Win,  const float* __restrict__ bin,
             const float* __restrict__ g1,   const float* __restrict__ b1)
{
    __shared__ float sWe[8][4];
    __shared__ float sWt[4][4];
    __shared__ float sbe[4];
    __shared__ float sred[16 * 8];
    __shared__ float sscale[4], sshift[4];

    const int t   = blockIdx.x;
    const int tid = threadIdx.x;   // 512

    if (tid < 32) {
        int k = tid >> 2, j = tid & 3;
        float acc = 0.f;
        #pragma unroll
        for (int m = 0; m < 8; m++) acc += Wobs[k * 8 + m] * Win[m * 4 + j];
        sWe[k][j] = acc;
    } else if (tid < 48) {
        int k = (tid - 32) >> 2, j = tid & 3;
        sWt[k][j] = Win[(8 + k) * 4 + j];
    } else if (tid < 52) {
        int j = tid - 48;
        float acc = bin[j];
        #pragma unroll
        for (int m = 0; m < 8; m++) acc += bobs[m] * Win[m * 4 + j];
        sbe[j] = acc;
    }
    __syncthreads();

    float z[8][4];
    float ps[4] = {0.f, 0.f, 0.f, 0.f};
    float pq[4] = {0.f, 0.f, 0.f, 0.f};

    const float4* obs4 = ((const float4*)obs) + (size_t)t * BATCH * 2;
    const float4* ts4  = ((const float4*)ts)  + (size_t)t * BATCH;

    #pragma unroll
    for (int s = 0; s < 8; s++) {
        int b = tid + s * 512;
        float4 o0 = obs4[b * 2 + 0];
        float4 o1 = obs4[b * 2 + 1];
        float4 tv = ts4[b];
        #pragma unroll
        for (int j = 0; j < 4; j++) {
            float a = sbe[j];
            a += o0.x * sWe[0][j] + o0.y * sWe[1][j] + o0.z * sWe[2][j] + o0.w * sWe[3][j];
            a += o1.x * sWe[4][j] + o1.y * sWe[5][j] + o1.z * sWe[6][j] + o1.w * sWe[7][j];
            a += tv.x * sWt[0][j] + tv.y * sWt[1][j] + tv.z * sWt[2][j] + tv.w * sWt[3][j];
            z[s][j] = a;
            ps[j] += a;
            pq[j] += a * a;
        }
    }

    const int lane = tid & 31, wrp = tid >> 5;
    #pragma unroll
    for (int j = 0; j < 4; j++) {
        #pragma unroll
        for (int off = 16; off; off >>= 1) {
            ps[j] += __shfl_xor_sync(0xffffffffu, ps[j], off);
            pq[j] += __shfl_xor_sync(0xffffffffu, pq[j], off);
        }
    }
    if (lane == 0) {
        #pragma unroll
        for (int j = 0; j < 4; j++) { sred[wrp * 8 + j] = ps[j]; sred[wrp * 8 + 4 + j] = pq[j]; }
    }
    __syncthreads();
    if (tid < 4) {
        float s0 = 0.f, q0 = 0.f;
        #pragma unroll
        for (int w = 0; w < 16; w++) { s0 += sred[w * 8 + tid]; q0 += sred[w * 8 + 4 + tid]; }
        float m  = s0 * (1.0f / BATCH);
        float v  = q0 * (1.0f / BATCH) - m * m;
        float sc = g1[tid] * rsqrtf(v + 1e-5f);
        sscale[tid] = sc;
        sshift[tid] = b1[tid] - m * sc;
    }
    __syncthreads();

    float4* Up = g_U + (size_t)t * BATCH;
    #pragma unroll
    for (int s = 0; s < 8; s++) {
        int b = tid + s * 512;
        float4 u;
        u.x = fmaxf(z[s][0] * sscale[0] + sshift[0], 0.f);
        u.y = fmaxf(z[s][1] * sscale[1] + sshift[1], 0.f);
        u.z = fmaxf(z[s][2] * sscale[2] + sshift[2], 0.f);
        u.w = fmaxf(z[s][3] * sscale[3] + sshift[3], 0.f);
        Up[b] = u;
    }
}

// ---------------------------------------------------------------------------
// Pass 2: sequential LSTM recurrence, single chain per thread, explicitly
// software-pipelined one step ahead:
//   program order per step = [shfls] -> [NEXT step's u-FMAs (filler in the
//   shfl shadow)] -> [hh-FMAs] -> [activations] -> [store].
// Depth-16 u-prefetch ring (~16 steps lead) rules out marginal DRAM-latency
// coverage. 128 blocks x 128 threads (one warp per SMSP).
// ---------------------------------------------------------------------------
__global__ void __launch_bounds__(128, 1)
pass2_kernel(const float* __restrict__ Wih, const float* __restrict__ Whh,
             const float* __restrict__ bih, const float* __restrict__ bhh)
{
    const int lane = threadIdx.x & 31;
    const int wid  = threadIdx.x >> 5;     // 0..3 -> SMSP
    const int e    = lane >> 2;            // 0..7
    const int k    = lane & 3;             // gate-row slice
    const int b    = blockIdx.x * 32 + wid * 8 + e;

    // Gate rows for this lane: i=k, f=4+k, g=8+k, o=12+k.
    float wiI[4], wiF[4], wiG[4], wiO[4];       // u-weights (natural order)
    float whI[4], whF[4], whG[4], whO[4];       // h-weights permuted: [d] = row[k^d]
    #pragma unroll
    for (int m = 0; m < 4; m++) {
        wiI[m] = Wih[(k     ) * 4 + m];
        wiF[m] = Wih[(4 + k ) * 4 + m];
        wiG[m] = Wih[(8 + k ) * 4 + m];
        wiO[m] = Wih[(12 + k) * 4 + m];
        int km = k ^ m;
        whI[m] = Whh[(k     ) * 4 + km];
        whF[m] = Whh[(4 + k ) * 4 + km];
        whG[m] = Whh[(8 + k ) * 4 + km];
        whO[m] = Whh[(12 + k) * 4 + km];
    }
    const float bI = bih[k]      + bhh[k];
    const float bF = bih[4 + k]  + bhh[4 + k];
    const float bG = bih[8 + k]  + bhh[8 + k];
    const float bO = bih[12 + k] + bhh[12 + k];

    float hk = 0.f, c = 0.f;

    const float4* __restrict__ up = g_U + b;
    float* __restrict__ hp = ((float*)g_H) + (size_t)b * 4 + k;

    // Depth-16 prefetch ring.
    float4 ub[16];
    #pragma unroll
    for (int i = 0; i < 16; i++) ub[i] = up[(size_t)i * BATCH];
    up += (size_t)16 * BATCH;

    // a-part for step 0 (preamble).
    float aI, aF, aG, aO;
    {
        float4 u = ub[0];
        aI = bI + u.x * wiI[0] + u.y * wiI[1] + u.z * wiI[2] + u.w * wiI[3];
        aF = bF + u.x * wiF[0] + u.y * wiF[1] + u.z * wiF[2] + u.w * wiF[3];
        aG = bG + u.x * wiG[0] + u.y * wiG[1] + u.z * wiG[2] + u.w * wiG[3];
        aO = bO + u.x * wiO[0] + u.y * wiO[1] + u.z * wiO[2] + u.w * wiO[3];
    }

// One step: shfls first, then next-step u-FMAs as explicit filler, then the
// dependent tail. LAST distinguishes the final step (no next-a needed).
#define P2_STEP(i, PF, LAST)                                                   \
    {                                                                          \
        /* 1. gathers of peer h (critical path head) */                        \
        float ha = __shfl_xor_sync(0xffffffffu, hk, 1);                        \
        float hb = __shfl_xor_sync(0xffffffffu, hk, 2);                        \
        float hc = __shfl_xor_sync(0xffffffffu, hk, 3);                        \
        /* 2. refill the slot just freed (16-step lead) */                     \
        if (PF) ub[i] = up[(size_t)(i) * BATCH];                               \
        /* 3. filler: NEXT step's u-part in the shfl/MUFU shadow */            \
        float nI = 0.f, nF = 0.f, nG = 0.f, nO = 0.f;                          \
        if (!LAST) {                                                           \
            float4 un = ub[((i) + 1) & 15];                                    \
            nI = bI + un.x * wiI[0] + un.y * wiI[1] + un.z * wiI[2] + un.w * wiI[3]; \
            nF = bF + un.x * wiF[0] + un.y * wiF[1] + un.z * wiF[2] + un.w * wiF[3]; \
            nG = bG + un.x * wiG[0] + un.y * wiG[1] + un.z * wiG[2] + un.w * wiG[3]; \
            nO = bO + un.x * wiO[0] + un.y * wiO[1] + un.z * wiO[2] + un.w * wiO[3]; \
        }                                                                      \
        /* 4. dependent tail */                                                \
        float gI = aI + ((hk * whI[0] + ha * whI[1]) + (hb * whI[2] + hc * whI[3])); \
        float gF = aF + ((hk * whF[0] + ha * whF[1]) + (hb * whF[2] + hc * whF[3])); \
        float gG = aG + ((hk * whG[0] + ha * whG[1]) + (hb * whG[2] + hc * whG[3])); \
        float gO = aO + ((hk * whO[0] + ha * whO[1]) + (hb * whO[2] + hc * whO[3])); \
        c  = sig_a(gF) * c + sig_a(gI) * tanh_a(gG);                           \
        hk = sig_a(gO) * tanh_a(c);                                            \
        hp[0] = hk;                                                            \
        hp += (size_t)BATCH * 4;                                               \
        aI = nI; aF = nF; aG = nG; aO = nO;                                    \
    }

    for (int t = 0; t < S - 16; t += 16) {
        #pragma unroll
        for (int i = 0; i < 16; i++) P2_STEP(i, true, false)
        up += (size_t)16 * BATCH;
    }
    #pragma unroll
    for (int i = 0; i < 16; i++) P2_STEP(i, false, (i == 15))
#undef P2_STEP
}

// ---------------------------------------------------------------------------
// Pass 3: one CTA (1024 thr) per timestep; 4 elements/thread cached in regs.
// BN2 stats over batch, y = BN2(h)@W_out + b_out, stats folded into [4x8]+[8].
// ---------------------------------------------------------------------------
__global__ void __launch_bounds__(1024, 1)
pass3_kernel(float* __restrict__ out,
             const float* __restrict__ g2,   const float* __restrict__ b2,
             const float* __restrict__ Wout, const float* __restrict__ bout)
{
    __shared__ float sred[32 * 8];
    __shared__ float sscale[4], sshift[4];
    __shared__ float sW[4][8];
    __shared__ float sB[8];

    const int t   = blockIdx.x;
    const int tid = threadIdx.x;   // 1024

    const float4* Hp = g_H + (size_t)t * BATCH;

    float4 hv[4];
    float ps[4] = {0.f, 0.f, 0.f, 0.f};
    float pq[4] = {0.f, 0.f, 0.f, 0.f};
    #pragma unroll
    for (int s = 0; s < 4; s++) {
        int b = tid + s * 1024;
        float4 v = Hp[b];
        hv[s] = v;
        ps[0] += v.x; pq[0] += v.x * v.x;
        ps[1] += v.y; pq[1] += v.y * v.y;
        ps[2] += v.z; pq[2] += v.z * v.z;
        ps[3] += v.w; pq[3] += v.w * v.w;
    }

    const int lane = tid & 31, wrp = tid >> 5;
    #pragma unroll
    for (int j = 0; j < 4; j++) {
        #pragma unroll
        for (int off = 16; off; off >>= 1) {
            ps[j] += __shfl_xor_sync(0xffffffffu, ps[j], off);
            pq[j] += __shfl_xor_sync(0xffffffffu, pq[j], off);
        }
    }
    if (lane == 0) {
        #pragma unroll
        for (int j = 0; j < 4; j++) { sred[wrp * 8 + j] = ps[j]; sred[wrp * 8 + 4 + j] = pq[j]; }
    }
    __syncthreads();
    if (tid < 4) {
        float s0 = 0.f, q0 = 0.f;
        #pragma unroll
        for (int w = 0; w < 32; w++) { s0 += sred[w * 8 + tid]; q0 += sred[w * 8 + 4 + tid]; }
        float m  = s0 * (1.0f / BATCH);
        float v  = q0 * (1.0f / BATCH) - m * m;
        float sc = g2[tid] * rsqrtf(v + 1e-5f);
        sscale[tid] = sc;
        sshift[tid] = b2[tid] - m * sc;
    }
    __syncthreads();
    if (tid < 32) {
        int kk = tid >> 3, j = tid & 7;
        sW[kk][j] = sscale[kk] * Wout[kk * 8 + j];
    } else if (tid < 40) {
        int j = tid - 32;
        float acc = bout[j];
        #pragma unroll
        for (int kk = 0; kk < 4; kk++) acc += sshift[kk] * Wout[kk * 8 + j];
        sB[j] = acc;
    }
    __syncthreads();

    float4* out4 = ((float4*)out) + (size_t)t * BATCH * 2;
    #pragma unroll
    for (int s = 0; s < 4; s++) {
        int b = tid + s * 1024;
        float4 v = hv[s];
        float y[8];
        #pragma unroll
        for (int j = 0; j < 8; j++) {
            y[j] = sB[j] + v.x * sW[0][j] + v.y * sW[1][j] + v.z * sW[2][j] + v.w * sW[3][j];
        }
        out4[b * 2 + 0] = make_float4(y[0], y[1], y[2], y[3]);
        out4[b * 2 + 1] = make_float4(y[4], y[5], y[6], y[7]);
    }
}

// ---------------------------------------------------------------------------
extern "C" void kernel_launch(void* const* d_in, const int* in_sizes, int n_in,
                              void* d_out, int out_size)
{
    const float* obs  = (const float*)d_in[0];
    const float* ts   = (const float*)d_in[1];
    const float* Wobs = (const float*)d_in[2];
    const float* bobs = (const float*)d_in[3];
    const float* Win  = (const float*)d_in[4];
    const float* bin  = (const float*)d_in[5];
    const float* g1   = (const float*)d_in[6];
    const float* b1   = (const float*)d_in[7];
    const float* Wih  = (const float*)d_in[8];
    const float* Whh  = (const float*)d_in[9];
    const float* bih  = (const float*)d_in[10];
    const float* bhh  = (const float*)d_in[11];
    const float* g2   = (const float*)d_in[12];
    const float* b2   = (const float*)d_in[13];
    const float* Wout = (const float*)d_in[14];
    const float* bout = (const float*)d_in[15];

    pass1_kernel<<<S, 512>>>(obs, ts, Wobs, bobs, Win, bin, g1, b1);
    pass2_kernel<<<BATCH / 32, 128>>>(Wih, Whh, bih, bhh);
    pass3_kernel<<<S, 1024>>>((float*)d_out, g2, b2, Wout, bout);
}